// round 15
// baseline (speedup 1.0000x reference)
#include <cuda_runtime.h>
#include <cstdint>

// LogLinearAttention — algebraic collapse (exact; rel_err=0 every round):
//   out[b] = sigmoid( sum_{s,e} x[b,s,e]*c[e] + S*(br·Wl) + bl ),
//   c[e] = sum_d Wl[d]*Wr[d,e].  q/v projections are dead.
//
// R12: every LDG-based x-stream variant measured ~3 TB/s regardless of shape
// (R3/R8/R11 ncu). Switch the stream to the TMA bulk path (cp.async.bulk ->
// UBLKCP), which issues full-line requests without per-warp L1tex queue
// exposure; reduce from SMEM. k_c / k_final byte-identical to 12.77 baseline.

#define BB 8
#define SS 2048
#define DD 512
#define DD4 (DD / 4)              // 128 float4 columns
#define CBLK_D 16                 // d-chunks for c partials
#define CBLK_E 16                 // e-chunks for c partials
#define DCH (DD / CBLK_D)         // 32 d rows per chunk
#define ECH4 (DD4 / CBLK_E)       // 8 float4 cols per chunk
#define JPB 37                    // row-range blocks per batch (296 = 2*148)
#define NBLK (BB * JPB)
#define ROWB (DD * 4)             // 2048 bytes per row
#define CHUNK 8192                // TMA chunk bytes (4 rows)
#define CF4 (CHUNK / 16)          // 512 float4 per chunk
#define NSTG 4                    // pipeline depth

__device__ float g_cpart[CBLK_D * DD];  // c partials over d-chunks (32 KB)
__device__ float g_dots[NBLK];          // per-block partial dots

__device__ __forceinline__ uint32_t smem_u32(const void* p) {
    uint32_t a;
    asm("{ .reg .u64 t; cvta.to.shared.u64 t, %1; cvt.u32.u64 %0, t; }"
        : "=r"(a) : "l"(p));
    return a;
}
__device__ __forceinline__ void mbar_init(uint32_t mbar, uint32_t cnt) {
    asm volatile("mbarrier.init.shared.b64 [%0], %1;" :: "r"(mbar), "r"(cnt) : "memory");
}
__device__ __forceinline__ void mbar_expect_tx(uint32_t mbar, uint32_t bytes) {
    asm volatile("mbarrier.arrive.expect_tx.shared.b64 _, [%0], %1;"
                 :: "r"(mbar), "r"(bytes) : "memory");
}
__device__ __forceinline__ void bulk_g2s(uint32_t dst, const void* src,
                                         uint32_t bytes, uint32_t mbar) {
    asm volatile(
        "cp.async.bulk.shared::cluster.global.mbarrier::complete_tx::bytes "
        "[%0], [%1], %2, [%3];"
        :: "r"(dst), "l"(src), "r"(bytes), "r"(mbar) : "memory");
}
__device__ __forceinline__ void mbar_wait(uint32_t mbar, uint32_t phase) {
    asm volatile(
        "{\n\t.reg .pred P;\n\t"
        "LW_%=:\n\t"
        "mbarrier.try_wait.parity.acquire.cta.shared::cta.b64 P, [%0], %1, 0x989680;\n\t"
        "@P bra LD_%=;\n\t"
        "bra LW_%=;\n\t"
        "LD_%=:\n\t}"
        :: "r"(mbar), "r"(phase) : "memory");
}

// ── k_c: UNCHANGED from the 12.77us baseline ──
__global__ void __launch_bounds__(256) k_c(
    const float* __restrict__ Wr,
    const float* __restrict__ Wl)
{
    const int jd = blockIdx.x >> 4;
    const int je = blockIdx.x & 15;
    const int td = threadIdx.x >> 3;
    const int tf = threadIdx.x & 7;

    const int d  = jd * DCH + td;
    const int e4 = je * ECH4 + tf;

    const float  wl = __ldg(&Wl[d]);
    const float4 w  = reinterpret_cast<const float4*>(Wr)[(size_t)d * DD4 + e4];

    __shared__ float4 s[DCH][ECH4];
    s[td][tf] = make_float4(wl * w.x, wl * w.y, wl * w.z, wl * w.w);
    __syncthreads();

#pragma unroll
    for (int off = DCH / 2; off > 0; off >>= 1) {
        if (td < off) {
            float4 a = s[td][tf], bq = s[td + off][tf];
            s[td][tf] = make_float4(a.x + bq.x, a.y + bq.y, a.z + bq.z, a.w + bq.w);
        }
        __syncthreads();
    }
    if (td == 0)
        reinterpret_cast<float4*>(g_cpart)[(size_t)jd * DD4 + e4] = s[0][tf];
}

// ── k_main: TMA bulk pipeline. 296 blocks x 256 threads. ──
__global__ void __launch_bounds__(256) k_main(
    const float* __restrict__ x)
{
    __shared__ __align__(16) float4 buf[NSTG][CF4];            // 4 x 8 KB
    __shared__ __align__(8) unsigned long long mbar_s[NSTG];

    const int tid = threadIdx.x;
    const int blk = blockIdx.x;
    const int b   = blk / JPB;
    const int j   = blk % JPB;

    uint32_t mb[NSTG], ba[NSTG];
#pragma unroll
    for (int i = 0; i < NSTG; ++i) {
        mb[i] = smem_u32(&mbar_s[i]);
        ba[i] = smem_u32(&buf[i][0]);
    }
    if (tid == 0) {
#pragma unroll
        for (int i = 0; i < NSTG; ++i) mbar_init(mb[i], 1);
        asm volatile("fence.proxy.async.shared::cta;" ::: "memory");
    }
    __syncthreads();

    // this thread owns float4 indices 2*tid, 2*tid+1 of every chunk
    const int col0 = (2 * tid) & (DD4 - 1);          // even column
    float4 c4a = make_float4(0.f, 0.f, 0.f, 0.f);
    float4 c4b = make_float4(0.f, 0.f, 0.f, 0.f);
#pragma unroll
    for (int jd = 0; jd < CBLK_D; ++jd) {
        float4 va = reinterpret_cast<const float4*>(g_cpart)[(size_t)jd * DD4 + col0];
        float4 vb = reinterpret_cast<const float4*>(g_cpart)[(size_t)jd * DD4 + col0 + 1];
        c4a.x += va.x; c4a.y += va.y; c4a.z += va.z; c4a.w += va.w;
        c4b.x += vb.x; c4b.y += vb.y; c4b.z += vb.z; c4b.w += vb.w;
    }

    const int r_begin = (j * SS) / JPB;
    const int r_end   = ((j + 1) * SS) / JPB;
    const char* src   = reinterpret_cast<const char*>(x)
                      + ((size_t)b * SS + r_begin) * ROWB;
    const int total   = (r_end - r_begin) * ROWB;            // 55-56 rows
    const int nch     = (total + CHUNK - 1) / CHUNK;         // 14 chunks

    // prologue: fill the pipeline
    if (tid == 0) {
        const int npro = nch < NSTG ? nch : NSTG;
        for (int i = 0; i < npro; ++i) {
            const uint32_t sz = (uint32_t)min(CHUNK, total - i * CHUNK);
            mbar_expect_tx(mb[i], sz);
            bulk_g2s(ba[i], src + (size_t)i * CHUNK, sz, mb[i]);
        }
    }

    float acc = 0.f;
    const int i0 = 2 * tid, i1 = 2 * tid + 1;        // float4 idx within chunk
    for (int i = 0; i < nch; ++i) {
        const int st = i & (NSTG - 1);
        const uint32_t ph = (uint32_t)((i / NSTG) & 1);
        mbar_wait(mb[st], ph);

        const int szf4 = min(CHUNK, total - i * CHUNK) >> 4;  // float4 count
        if (i0 < szf4) {
            float4 v = buf[st][i0];
            acc += v.x * c4a.x + v.y * c4a.y + v.z * c4a.z + v.w * c4a.w;
        }
        if (i1 < szf4) {
            float4 v = buf[st][i1];
            acc += v.x * c4b.x + v.y * c4b.y + v.z * c4b.z + v.w * c4b.w;
        }
        __syncthreads();                              // all reads of buf[st] done

        if (tid == 0 && i + NSTG < nch) {
            const int o2 = (i + NSTG) * CHUNK;
            const uint32_t sz = (uint32_t)min(CHUNK, total - o2);
            mbar_expect_tx(mb[st], sz);
            bulk_g2s(ba[st], src + (size_t)o2, sz, mb[st]);
        }
    }

    // block-reduce 256 scalars (validated epilogue)
#pragma unroll
    for (int off = 16; off > 0; off >>= 1)
        acc += __shfl_down_sync(0xffffffffu, acc, off);
    __shared__ float warp_s[8];
    if ((tid & 31) == 0) warp_s[tid >> 5] = acc;
    __syncthreads();
    if (tid == 0) {
        float t = warp_s[0];
#pragma unroll
        for (int i = 1; i < 8; ++i) t += warp_s[i];
        g_dots[blk] = t;
    }
}

// ── k_final: UNCHANGED from the 12.77us baseline ──
__global__ void __launch_bounds__(512) k_final(
    const float* __restrict__ br,
    const float* __restrict__ Wl,
    const float* __restrict__ bl,
    float* __restrict__ out)
{
    const int tid = threadIdx.x;
    __shared__ float warp_s[16];
    __shared__ float s_bias;

    if (tid < 128) {
        const float4 br4 = reinterpret_cast<const float4*>(br)[tid];
        const float4 wl4 = reinterpret_cast<const float4*>(Wl)[tid];
        float bv = br4.x * wl4.x + br4.y * wl4.y + br4.z * wl4.z + br4.w * wl4.w;
#pragma unroll
        for (int off = 16; off > 0; off >>= 1)
            bv += __shfl_down_sync(0xffffffffu, bv, off);
        if ((tid & 31) == 0) warp_s[tid >> 5] = bv;
    }
    __syncthreads();
    if (tid == 0) s_bias = warp_s[0] + warp_s[1] + warp_s[2] + warp_s[3];
    __syncthreads();

    const int b = tid >> 6;
    const int i = tid & 63;
    float d = (i < JPB) ? g_dots[b * JPB + i] : 0.f;
#pragma unroll
    for (int off = 16; off > 0; off >>= 1)
        d += __shfl_down_sync(0xffffffffu, d, off);
    __shared__ float half_s[16];
    if ((tid & 31) == 0) half_s[tid >> 5] = d;
    __syncthreads();
    if (i == 0) {
        float z = half_s[(tid >> 5)] + half_s[(tid >> 5) + 1] + (float)SS * s_bias + bl[0];
        out[b] = 1.0f / (1.0f + expf(-z));
    }
}

extern "C" void kernel_launch(void* const* d_in, const int* in_sizes, int n_in,
                              void* d_out, int out_size)
{
    // metadata order: x, Wq, bq, Wv, bv, Wr, br, Wl, bl
    const float* x  = (const float*)d_in[0];
    const float* Wr = (const float*)d_in[5];
    const float* br = (const float*)d_in[6];
    const float* Wl = (const float*)d_in[7];
    const float* bl = (const float*)d_in[8];
    float* out = (float*)d_out;

    k_c<<<CBLK_D * CBLK_E, 256>>>(Wr, Wl);
    k_main<<<NBLK, 256>>>(x);
    k_final<<<1, 512>>>(br, Wl, bl, out);
}

// round 16
// speedup vs baseline: 1.3458x; 1.3458x over previous
#include <cuda_runtime.h>

// LogLinearAttention — algebraic collapse (exact; rel_err=0 every round):
//   softmax over axis=1 then sum over axis=1 => attention columns sum to 1:
//     out[b] = sigmoid( sum_{s,e} x[b,s,e]*c[e] + S*(br·Wl) + bl )
//   c[e] = sum_d Wl[d]*Wr[d,e].  q/v projections are dead.
//
// R13: single kernel (one launch), 296 blocks = perfect 2/SM wave.
// vs R11: c is produced FULLY FOLDED by 8 producer blocks (one 64-float
// slice each, j==0 of each batch, row-compensated), so the 296 stream
// epilogues read ONE float4 of c instead of folding 16 partials.
// Stream loop is the validated 5.4TB/s shape. Ticket finisher, counter reset.

#define BB 8
#define SS 2048
#define DD 512
#define DD4 (DD / 4)              // 128 float4 columns
#define JPB 37                    // blocks per batch
#define NBLK (BB * JPB)           // 296 = 2 * 148
#define CROWS 24                  // stream rows for the 8 c-duty blocks
#define RREST (SS - CROWS)        // 2024 rows split across the other 36 blocks

__device__ float g_c[DD];               // FINAL c (2 KB)
__device__ float g_dots[NBLK];          // per-block partial dots
__device__ int   g_cdone;               // c-slice completion counter (8)
__device__ int   g_done;                // block completion counter

__global__ void __launch_bounds__(256) k_all(
    const float* __restrict__ x,
    const float* __restrict__ Wr,
    const float* __restrict__ Wl,
    const float* __restrict__ br,
    const float* __restrict__ bl,
    float* __restrict__ out)
{
    const int blk = blockIdx.x;
    const int tid = threadIdx.x;
    const int b   = blk / JPB;
    const int j   = blk % JPB;

    // ── c-duty prologue: 8 blocks (j==0), block b computes c[e] for its
    //    64-float slice e in [b*64, b*64+64), fully folded over all 512 d ──
    if (j == 0) {
        const int tf = tid & 15;                  // float4 col in slice 0..15
        const int td = tid >> 4;                  // d-subgroup 0..15 (32 rows each)
        const int e4 = b * 16 + tf;               // global float4 column

        float4 acc = make_float4(0.f, 0.f, 0.f, 0.f);
#pragma unroll 8
        for (int k = 0; k < 32; ++k) {            // 32 independent loads
            const int d = td * 32 + k;
            const float wl = __ldg(&Wl[d]);
            const float4 w = reinterpret_cast<const float4*>(Wr)[(size_t)d * DD4 + e4];
            acc.x += wl * w.x; acc.y += wl * w.y; acc.z += wl * w.z; acc.w += wl * w.w;
        }

        __shared__ float4 s[16][16];              // 4 KB
        s[td][tf] = acc;
        __syncthreads();
#pragma unroll
        for (int off = 8; off > 0; off >>= 1) {
            if (td < off) {
                float4 a = s[td][tf], b2 = s[td + off][tf];
                s[td][tf] = make_float4(a.x + b2.x, a.y + b2.y, a.z + b2.z, a.w + b2.w);
            }
            __syncthreads();
        }
        if (td == 0) {
            reinterpret_cast<float4*>(g_c)[e4] = s[0][tf];
            __threadfence();
        }
        __syncthreads();
        if (tid == 0) atomicAdd(&g_cdone, 1);
        __syncthreads();
    }

    // ── streaming: validated loop shape, xsum accumulation in registers ──
    const int col = tid & (DD4 - 1);          // float4 column 0..127
    const int r0  = tid >> 7;                 // 0 or 1

    // compensated partition: c-duty block gets 24 rows, others ~56
    const int r_begin = (j == 0) ? 0 : CROWS + ((j - 1) * RREST) / (JPB - 1);
    const int r_end   = (j == 0) ? CROWS : CROWS + (j * RREST) / (JPB - 1);
    const float4* xb  = reinterpret_cast<const float4*>(x + (size_t)b * SS * DD);

    float4 acc = make_float4(0.f, 0.f, 0.f, 0.f);
    int r = r_begin + r0;
#pragma unroll 4
    for (; r < r_end; r += 2) {               // continuous stream, MLP_p1 ~ 4
        float4 v = xb[(size_t)r * DD4 + col];
        acc.x += v.x; acc.y += v.y; acc.z += v.z; acc.w += v.w;
    }

    // ── tail: c availability guard (producers finish far earlier) ──
    if (tid == 0) {
        while (*(volatile int*)&g_cdone < BB) { }
    }
    __syncthreads();
    __threadfence();

    const float4 c4 = reinterpret_cast<const float4*>(g_c)[col];   // ONE load
    float val = acc.x * c4.x + acc.y * c4.y + acc.z * c4.z + acc.w * c4.w;

#pragma unroll
    for (int off = 16; off > 0; off >>= 1)
        val += __shfl_down_sync(0xffffffffu, val, off);
    __shared__ float warp_s[8];
    if ((tid & 31) == 0) warp_s[tid >> 5] = val;
    __syncthreads();

    __shared__ int s_last;
    if (tid == 0) {
        float t = warp_s[0];
#pragma unroll
        for (int i = 1; i < 8; ++i) t += warp_s[i];
        g_dots[blk] = t;
        __threadfence();
        s_last = (atomicAdd(&g_done, 1) == NBLK - 1);
    }
    __syncthreads();
    if (!s_last) return;

    // ── last block: bias dot + per-batch fold + sigmoid + counter reset ──
    __threadfence();

    __shared__ float bias_w[4];
    __shared__ float s_bias;
    if (tid < 128) {
        const float4 br4 = reinterpret_cast<const float4*>(br)[tid];
        const float4 wl4 = reinterpret_cast<const float4*>(Wl)[tid];
        float bv = br4.x * wl4.x + br4.y * wl4.y + br4.z * wl4.z + br4.w * wl4.w;
#pragma unroll
        for (int off = 16; off > 0; off >>= 1)
            bv += __shfl_down_sync(0xffffffffu, bv, off);
        if ((tid & 31) == 0) bias_w[tid >> 5] = bv;
    }
    __syncthreads();
    if (tid == 0) s_bias = bias_w[0] + bias_w[1] + bias_w[2] + bias_w[3];
    __syncthreads();

    // warp w = batch w (8 warps); lanes fold the 37 dots of that batch
    {
        const int w    = tid >> 5;
        const int lane = tid & 31;
        float d = (lane < JPB) ? g_dots[w * JPB + lane] : 0.f;
        if (lane + 32 < JPB) d += g_dots[w * JPB + lane + 32];   // lanes 0..4
#pragma unroll
        for (int off = 16; off > 0; off >>= 1)
            d += __shfl_down_sync(0xffffffffu, d, off);
        if (lane == 0) {
            float z = d + (float)SS * s_bias + bl[0];
            out[w] = 1.0f / (1.0f + expf(-z));
        }
    }

    __syncthreads();
    if (tid == 0) { g_done = 0; g_cdone = 0; }
}

extern "C" void kernel_launch(void* const* d_in, const int* in_sizes, int n_in,
                              void* d_out, int out_size)
{
    // metadata order: x, Wq, bq, Wv, bv, Wr, br, Wl, bl
    const float* x  = (const float*)d_in[0];
    const float* Wr = (const float*)d_in[5];
    const float* br = (const float*)d_in[6];
    const float* Wl = (const float*)d_in[7];
    const float* bl = (const float*)d_in[8];
    float* out = (float*)d_out;

    k_all<<<NBLK, 256>>>(x, Wr, Wl, br, bl, out);
}